// round 1
// baseline (speedup 1.0000x reference)
#include <cuda_runtime.h>

#define BN 8192
#define CN 16
#define DN 256
#define RN 64
#define EN 32
#define ORDN 16
#define LN 32

#define BT 64   // bodies per CTA in quad kernel
#define TJ 64   // j-tile width

// Scratch (allocation-free rule: __device__ globals)
__device__ float g_q[BN * CN];    // ||A_c^T z_b||^2
__device__ float g_w[CN * DN];    // w_c = A_c A_c^T mu_c
__device__ float g_s0[CN];        // ||A_c^T mu_c||^2

// ---------------------------------------------------------------------------
// Kernel P: per-class precompute. grid = C, block = D threads.
// m_j = sum_i A[i,j] mu_i ; w_i = sum_j A[i,j] m_j ; s0 = ||m||^2
// ---------------------------------------------------------------------------
__global__ void precompute_kernel(const float* __restrict__ mu,
                                  const float* __restrict__ sig) {
    const int c = blockIdx.x;
    const int j = threadIdx.x;
    __shared__ float mus[DN];
    __shared__ float ms[DN];
    __shared__ float red[DN];

    mus[j] = mu[c * DN + j];
    __syncthreads();

    const float* A = sig + (size_t)c * DN * DN;
    float m = 0.f;
#pragma unroll 4
    for (int i = 0; i < DN; i++) m += A[i * DN + j] * mus[i];
    ms[j] = m;
    red[j] = m * m;
    __syncthreads();

    float wi = 0.f;
#pragma unroll 4
    for (int jj = 0; jj < DN; jj++) wi += A[j * DN + jj] * ms[jj];
    g_w[c * DN + j] = wi;

    for (int off = 128; off > 0; off >>= 1) {
        if (j < off) red[j] += red[j + off];
        __syncthreads();
    }
    if (j == 0) g_s0[c] = red[0];
}

// ---------------------------------------------------------------------------
// Kernel A: q[b,c] = sum_j ( sum_i A[c,i,j] * z[b,i] )^2
// grid = (B/BT, C), block = 256 (16 tx x 16 ty), 4x4 register micro-tiles.
// Dynamic smem: Zs[BT][DN] + As[DN][TJ] = 128 KB.
// ---------------------------------------------------------------------------
__global__ __launch_bounds__(256) void quad_kernel(const float* __restrict__ z,
                                                   const float* __restrict__ sig) {
    extern __shared__ float sm[];
    float* Zs = sm;             // [BT][DN], b-major
    float* As = sm + BT * DN;   // [DN][TJ], k-major

    const int c   = blockIdx.y;
    const int b0  = blockIdx.x * BT;
    const int tid = threadIdx.x;
    const int tx  = tid & 15;   // j group
    const int ty  = tid >> 4;   // body group

    // Load z tile (vectorized, coalesced). Layout matches source directly.
    {
        const float4* zp = (const float4*)(z + (size_t)b0 * DN);
        float4* Zs4 = (float4*)Zs;
        for (int idx = tid; idx < BT * DN / 4; idx += 256) Zs4[idx] = zp[idx];
    }

    const float* Ac = sig + (size_t)c * DN * DN;
    float q[4] = {0.f, 0.f, 0.f, 0.f};

    for (int jt = 0; jt < DN; jt += TJ) {
        __syncthreads();  // previous tile's compute done (also covers Zs load)
        {
            float4* As4 = (float4*)As;
            for (int idx = tid; idx < DN * TJ / 4; idx += 256) {
                int i  = idx >> 4;   // row k (16 float4 per row)
                int jp = idx & 15;   // float4 within row
                As4[idx] = *(const float4*)(Ac + (size_t)i * DN + jt + jp * 4);
            }
        }
        __syncthreads();

        float v[4][4];
#pragma unroll
        for (int bi = 0; bi < 4; bi++)
#pragma unroll
            for (int ji = 0; ji < 4; ji++) v[bi][ji] = 0.f;

#pragma unroll 4
        for (int k = 0; k < DN; k += 4) {
            float4 zf[4], af[4];
#pragma unroll
            for (int bi = 0; bi < 4; bi++)
                zf[bi] = *(const float4*)&Zs[(ty * 4 + bi) * DN + k];
#pragma unroll
            for (int kk = 0; kk < 4; kk++)
                af[kk] = *(const float4*)&As[(k + kk) * TJ + tx * 4];

#pragma unroll
            for (int kk = 0; kk < 4; kk++) {
                const float a0 = af[kk].x, a1 = af[kk].y;
                const float a2 = af[kk].z, a3 = af[kk].w;
#pragma unroll
                for (int bi = 0; bi < 4; bi++) {
                    const float zv = (kk == 0) ? zf[bi].x
                                   : (kk == 1) ? zf[bi].y
                                   : (kk == 2) ? zf[bi].z
                                               : zf[bi].w;
                    v[bi][0] += zv * a0;
                    v[bi][1] += zv * a1;
                    v[bi][2] += zv * a2;
                    v[bi][3] += zv * a3;
                }
            }
        }

#pragma unroll
        for (int bi = 0; bi < 4; bi++)
#pragma unroll
            for (int ji = 0; ji < 4; ji++) q[bi] += v[bi][ji] * v[bi][ji];
    }

    // Reduce q over the 16 tx columns
    __syncthreads();
    float* red = sm;  // reuse smem: [BT][16]
#pragma unroll
    for (int bi = 0; bi < 4; bi++) red[(ty * 4 + bi) * 16 + tx] = q[bi];
    __syncthreads();
    if (tid < BT) {
        float s = 0.f;
#pragma unroll
        for (int t = 0; t < 16; t++) s += red[tid * 16 + t];
        g_q[(size_t)(b0 + tid) * CN + c] = s;
    }
}

// ---------------------------------------------------------------------------
// Kernel B: d2 -> softmax -> ARX recursion -> weighted output.
// block = 256 threads = 16 bodies x 16 classes; grid = B/16.
// ---------------------------------------------------------------------------
__global__ __launch_bounds__(256) void arx_out_kernel(
    const float* __restrict__ y, const float* __restrict__ z,
    const float* __restrict__ u, const float* __restrict__ a_coef,
    const float* __restrict__ b_coef, const float* __restrict__ bias,
    float* __restrict__ out) {
    __shared__ float ps[16 * 16 * 33];  // [body][c][l], padded row of 33
    __shared__ float acs[CN * ORDN];
    __shared__ float bcs[CN * EN];
    __shared__ float bss[CN];

    const int tid = threadIdx.x;
    if (tid < CN * ORDN) acs[tid] = a_coef[tid];
    for (int i = tid; i < CN * EN; i += 256) bcs[i] = b_coef[i];
    if (tid < CN) bss[tid] = bias[tid];
    __syncthreads();

    const int tb = tid >> 4;  // body 0..15
    const int tc = tid & 15;  // class 0..15
    const int b  = blockIdx.x * 16 + tb;

    // lin = w_c . z_b  (w is 16KB -> L1-resident; z broadcasts across c-lanes)
    const float4* wv = (const float4*)(g_w + tc * DN);
    const float4* zv = (const float4*)(z + (size_t)b * DN);
    float lin = 0.f;
#pragma unroll 8
    for (int k = 0; k < DN / 4; k++) {
        float4 a = wv[k], zz = zv[k];
        lin += a.x * zz.x + a.y * zz.y + a.z * zz.z + a.w * zz.w;
    }

    float d2 = g_q[(size_t)b * CN + tc] - 2.f * lin + g_s0[tc];
    d2 = fmaxf(d2, 1e-8f);

    // softmax(-d2) within each 16-lane class group (xor masks 1,2,4,8 stay in-group)
    float mn = d2;
#pragma unroll
    for (int m = 8; m; m >>= 1) mn = fminf(mn, __shfl_xor_sync(0xffffffffu, mn, m));
    float e = expf(-(d2 - mn));
    float ssum = e;
#pragma unroll
    for (int m = 8; m; m >>= 1) ssum += __shfl_xor_sync(0xffffffffu, ssum, m);
    float psi = e / ssum;

    // ub = u[b,c,:] . b_coef[c,:] + bias[c]
    const float4* uv = (const float4*)(u + ((size_t)b * CN + tc) * EN);
    float ub = bss[tc];
#pragma unroll
    for (int k = 0; k < EN / 4; k++) {
        float4 uu = uv[k];
        const float* bc = &bcs[tc * EN + k * 4];
        ub += uu.x * bc[0] + uu.y * bc[1] + uu.z * bc[2] + uu.w * bc[3];
    }

    // ARX state: last ORDN samples of y[b,c,:]
    float s[ORDN];
    const float4* yv = (const float4*)(y + ((size_t)b * CN + tc) * RN + (RN - ORDN));
#pragma unroll
    for (int k = 0; k < ORDN / 4; k++) {
        float4 t = yv[k];
        s[k * 4 + 0] = t.x; s[k * 4 + 1] = t.y;
        s[k * 4 + 2] = t.z; s[k * 4 + 3] = t.w;
    }
    float ar[ORDN];
#pragma unroll
    for (int o = 0; o < ORDN; o++) ar[o] = acs[tc * ORDN + o];

    float* myps = &ps[(tb * 16 + tc) * 33];
#pragma unroll
    for (int l = 0; l < LN; l++) {
        float y0 = 0.f, y1 = 0.f;
#pragma unroll
        for (int o = 0; o < ORDN; o += 2) {
            y0 += s[o] * ar[o];
            y1 += s[o + 1] * ar[o + 1];
        }
        float yn = ub + y0 + y1;
#pragma unroll
        for (int o = 0; o < ORDN - 1; o++) s[o] = s[o + 1];
        s[ORDN - 1] = yn;
        myps[l] = psi * yn;
    }
    __syncthreads();

    // out[b, l] = sum_c psi_c * pred_{c,l}
    for (int o = tid; o < 16 * LN; o += 256) {
        int bb = o >> 5, l = o & 31;
        float acc = 0.f;
#pragma unroll
        for (int cc = 0; cc < CN; cc++) acc += ps[(bb * 16 + cc) * 33 + l];
        out[(size_t)(blockIdx.x * 16 + bb) * LN + l] = acc;
    }
}

// ---------------------------------------------------------------------------
extern "C" void kernel_launch(void* const* d_in, const int* in_sizes, int n_in,
                              void* d_out, int out_size) {
    const float* y      = (const float*)d_in[0];
    const float* z      = (const float*)d_in[1];
    const float* u      = (const float*)d_in[2];
    const float* mu     = (const float*)d_in[3];
    const float* sig    = (const float*)d_in[4];
    const float* a_coef = (const float*)d_in[5];
    const float* b_coef = (const float*)d_in[6];
    const float* bias   = (const float*)d_in[7];
    float* out = (float*)d_out;

    cudaFuncSetAttribute(quad_kernel,
                         cudaFuncAttributeMaxDynamicSharedMemorySize,
                         (BT * DN + DN * TJ) * sizeof(float));

    precompute_kernel<<<CN, DN>>>(mu, sig);
    quad_kernel<<<dim3(BN / BT, CN), 256, (BT * DN + DN * TJ) * sizeof(float)>>>(z, sig);
    arx_out_kernel<<<BN / 16, 256>>>(y, z, u, a_coef, b_coef, bias, out);
}

// round 2
// speedup vs baseline: 1.6069x; 1.6069x over previous
#include <cuda_runtime.h>

#define BN 8192
#define CN 16
#define DN 256
#define RN 64
#define EN 32
#define ORDN 16
#define LN 32

#define BT 64   // bodies per CTA in quad kernel
#define KT 32   // i-tile rows for the A tile

// Scratch (allocation-free rule: __device__ globals)
__device__ float g_q[BN * CN];    // d2[b,c] = ||A_c^T (mu_c - z_b)||^2

// ---------------------------------------------------------------------------
// packed f32x2 helpers
// ---------------------------------------------------------------------------
__device__ __forceinline__ unsigned long long pk2(float lo, float hi) {
    unsigned long long r;
    asm("mov.b64 %0, {%1, %2};" : "=l"(r) : "f"(lo), "f"(hi));
    return r;
}
__device__ __forceinline__ void upk2(unsigned long long v, float& lo, float& hi) {
    asm("mov.b64 {%0, %1}, %2;" : "=f"(lo), "=f"(hi) : "l"(v));
}
__device__ __forceinline__ unsigned long long ffma2(unsigned long long a,
                                                    unsigned long long b,
                                                    unsigned long long c) {
    unsigned long long d;
    asm("fma.rn.f32x2 %0, %1, %2, %3;" : "=l"(d) : "l"(a), "l"(b), "l"(c));
    return d;
}
__device__ __forceinline__ unsigned long long fadd2(unsigned long long a,
                                                    unsigned long long b) {
    unsigned long long d;
    asm("add.rn.f32x2 %0, %1, %2;" : "=l"(d) : "l"(a), "l"(b));
    return d;
}

// ---------------------------------------------------------------------------
// Kernel A: d2[b,c] = sum_j ( sum_i A[c,i,j] * (mu[c,i] - z[b,i]) )^2
// grid = (B/BT, C), block = 256 = 32 tx (j) x 8 ty (body).
// Per-thread 8x8 micro-tile, body pairs packed into f32x2 lanes.
// smem: Ds[DN][BT] (64KB, transposed diffs) + As[KT][DN] (32KB) = 96KB.
// ---------------------------------------------------------------------------
__global__ __launch_bounds__(256, 2) void quad_kernel(const float* __restrict__ z,
                                                      const float* __restrict__ mu,
                                                      const float* __restrict__ sig) {
    extern __shared__ float sm[];
    float* Ds = sm;             // [DN][BT]  : Ds[i][b] = mu[c,i] - z[b0+b,i]
    float* As = sm + DN * BT;   // [KT][DN]

    const int c   = blockIdx.y;
    const int b0  = blockIdx.x * BT;
    const int tid = threadIdx.x;
    const int tx  = tid & 31;   // j group: j in {4tx..4tx+3} U {128+4tx..+3}
    const int ty  = tid >> 5;   // body group: bodies 8ty..8ty+7 (warp == ty)

    // Load transposed diff tile. Lanes vary b -> STS conflict-free.
    // (z reads are 16B-scattered but z is L2-resident across the 16 c's.)
    for (int idx = tid; idx < BT * (DN / 4); idx += 256) {
        int b  = idx & (BT - 1);
        int kq = idx >> 6;  // 0..63 float4 group of i
        float4 zz = *(const float4*)(z + (size_t)(b0 + b) * DN + kq * 4);
        float4 mm = *(const float4*)(mu + c * DN + kq * 4);  // warp-uniform
        Ds[(kq * 4 + 0) * BT + b] = mm.x - zz.x;
        Ds[(kq * 4 + 1) * BT + b] = mm.y - zz.y;
        Ds[(kq * 4 + 2) * BT + b] = mm.z - zz.z;
        Ds[(kq * 4 + 3) * BT + b] = mm.w - zz.w;
    }

    const float* Ac = sig + (size_t)c * DN * DN;

    unsigned long long v[8][4];  // [jj][body-pair] accumulators (packed)
#pragma unroll
    for (int jj = 0; jj < 8; jj++)
#pragma unroll
        for (int bp = 0; bp < 4; bp++) v[jj][bp] = 0ull;

    for (int it = 0; it < DN; it += KT) {
        __syncthreads();
        // Load A rows [it, it+KT) x all j. Coalesced, conflict-free STS.
        for (int idx = tid; idx < KT * (DN / 4); idx += 256) {
            int j4 = idx & 63;
            int ii = idx >> 6;
            *(float4*)&As[ii * DN + j4 * 4] =
                *(const float4*)(Ac + (size_t)(it + ii) * DN + j4 * 4);
        }
        __syncthreads();

#pragma unroll 4
        for (int ii = 0; ii < KT; ii++) {
            // 8 bodies: two float4 = four natural f32x2 pairs (broadcast LDS)
            ulonglong2 za = *(const ulonglong2*)&Ds[(it + ii) * BT + ty * 8];
            ulonglong2 zb = *(const ulonglong2*)&Ds[(it + ii) * BT + ty * 8 + 4];
            unsigned long long z2[4] = {za.x, za.y, zb.x, zb.y};

            // 8 a values (two conflict-free float4s), duplicated into pairs
            float4 a0 = *(const float4*)&As[ii * DN + tx * 4];
            float4 a1 = *(const float4*)&As[ii * DN + 128 + tx * 4];
            unsigned long long ad[8] = {
                pk2(a0.x, a0.x), pk2(a0.y, a0.y), pk2(a0.z, a0.z), pk2(a0.w, a0.w),
                pk2(a1.x, a1.x), pk2(a1.y, a1.y), pk2(a1.z, a1.z), pk2(a1.w, a1.w)};

#pragma unroll
            for (int jj = 0; jj < 8; jj++)
#pragma unroll
                for (int bp = 0; bp < 4; bp++)
                    v[jj][bp] = ffma2(z2[bp], ad[jj], v[jj][bp]);
        }
    }

    // Square-accumulate over this thread's 8 j's (packed)
    unsigned long long q2[4] = {0ull, 0ull, 0ull, 0ull};
#pragma unroll
    for (int jj = 0; jj < 8; jj++)
#pragma unroll
        for (int bp = 0; bp < 4; bp++) q2[bp] = ffma2(v[jj][bp], v[jj][bp], q2[bp]);

    // Reduce over the 32 tx lanes (pure warp shuffle, packed adds)
#pragma unroll
    for (int m = 16; m; m >>= 1) {
#pragma unroll
        for (int bp = 0; bp < 4; bp++) {
            unsigned long long o = __shfl_xor_sync(0xffffffffu, q2[bp], m);
            q2[bp] = fadd2(q2[bp], o);
        }
    }
    if (tx == 0) {
#pragma unroll
        for (int bp = 0; bp < 4; bp++) {
            float lo, hi;
            upk2(q2[bp], lo, hi);
            int b = b0 + ty * 8 + bp * 2;
            g_q[(size_t)b * CN + c]       = lo;
            g_q[(size_t)(b + 1) * CN + c] = hi;
        }
    }
}

// ---------------------------------------------------------------------------
// Kernel B: d2 -> softmax -> ARX recursion -> weighted output.
// block = 256 threads = 16 bodies x 16 classes; grid = B/16.
// ---------------------------------------------------------------------------
__global__ __launch_bounds__(256) void arx_out_kernel(
    const float* __restrict__ y, const float* __restrict__ u,
    const float* __restrict__ a_coef, const float* __restrict__ b_coef,
    const float* __restrict__ bias, float* __restrict__ out) {
    __shared__ float ps[16 * 16 * 33];  // [body][c][l], padded row of 33
    __shared__ float acs[CN * ORDN];
    __shared__ float bcs[CN * EN];
    __shared__ float bss[CN];

    const int tid = threadIdx.x;
    if (tid < CN * ORDN) acs[tid] = a_coef[tid];
    for (int i = tid; i < CN * EN; i += 256) bcs[i] = b_coef[i];
    if (tid < CN) bss[tid] = bias[tid];
    __syncthreads();

    const int tb = tid >> 4;  // body 0..15
    const int tc = tid & 15;  // class 0..15
    const int b  = blockIdx.x * 16 + tb;

    float d2 = fmaxf(g_q[(size_t)b * CN + tc], 1e-8f);

    // softmax(-d2) within each 16-lane class group (xor masks 1,2,4,8 stay in-group)
    float mn = d2;
#pragma unroll
    for (int m = 8; m; m >>= 1) mn = fminf(mn, __shfl_xor_sync(0xffffffffu, mn, m));
    float e = expf(-(d2 - mn));
    float ssum = e;
#pragma unroll
    for (int m = 8; m; m >>= 1) ssum += __shfl_xor_sync(0xffffffffu, ssum, m);
    float psi = e / ssum;

    // ub = u[b,c,:] . b_coef[c,:] + bias[c]
    const float4* uv = (const float4*)(u + ((size_t)b * CN + tc) * EN);
    float ub = bss[tc];
#pragma unroll
    for (int k = 0; k < EN / 4; k++) {
        float4 uu = uv[k];
        const float* bc = &bcs[tc * EN + k * 4];
        ub += uu.x * bc[0] + uu.y * bc[1] + uu.z * bc[2] + uu.w * bc[3];
    }

    // ARX state: last ORDN samples of y[b,c,:]
    float s[ORDN];
    const float4* yv = (const float4*)(y + ((size_t)b * CN + tc) * RN + (RN - ORDN));
#pragma unroll
    for (int k = 0; k < ORDN / 4; k++) {
        float4 t = yv[k];
        s[k * 4 + 0] = t.x; s[k * 4 + 1] = t.y;
        s[k * 4 + 2] = t.z; s[k * 4 + 3] = t.w;
    }
    float ar[ORDN];
#pragma unroll
    for (int o = 0; o < ORDN; o++) ar[o] = acs[tc * ORDN + o];

    float* myps = &ps[(tb * 16 + tc) * 33];
#pragma unroll
    for (int l = 0; l < LN; l++) {
        float y0 = 0.f, y1 = 0.f;
#pragma unroll
        for (int o = 0; o < ORDN; o += 2) {
            y0 += s[o] * ar[o];
            y1 += s[o + 1] * ar[o + 1];
        }
        float yn = ub + y0 + y1;
#pragma unroll
        for (int o = 0; o < ORDN - 1; o++) s[o] = s[o + 1];
        s[ORDN - 1] = yn;
        myps[l] = psi * yn;
    }
    __syncthreads();

    // out[b, l] = sum_c psi_c * pred_{c,l}
    for (int o = tid; o < 16 * LN; o += 256) {
        int bb = o >> 5, l = o & 31;
        float acc = 0.f;
#pragma unroll
        for (int cc = 0; cc < CN; cc++) acc += ps[(bb * 16 + cc) * 33 + l];
        out[(size_t)(blockIdx.x * 16 + bb) * LN + l] = acc;
    }
}

// ---------------------------------------------------------------------------
extern "C" void kernel_launch(void* const* d_in, const int* in_sizes, int n_in,
                              void* d_out, int out_size) {
    const float* y      = (const float*)d_in[0];
    const float* z      = (const float*)d_in[1];
    const float* u      = (const float*)d_in[2];
    const float* mu     = (const float*)d_in[3];
    const float* sig    = (const float*)d_in[4];
    const float* a_coef = (const float*)d_in[5];
    const float* b_coef = (const float*)d_in[6];
    const float* bias   = (const float*)d_in[7];
    float* out = (float*)d_out;

    const int smem = (DN * BT + KT * DN) * sizeof(float);  // 96 KB
    cudaFuncSetAttribute(quad_kernel,
                         cudaFuncAttributeMaxDynamicSharedMemorySize, smem);

    quad_kernel<<<dim3(BN / BT, CN), 256, smem>>>(z, mu, sig);
    arx_out_kernel<<<BN / 16, 256>>>(y, u, a_coef, b_coef, bias, out);
}

// round 7
// speedup vs baseline: 1.8487x; 1.1505x over previous
#include <cuda_runtime.h>
#include <cstdint>

#define BN 8192
#define CN 16
#define DN 256
#define RN 64
#define EN 32
#define ORDN 16
#define LN 32

#define MT 128   // bodies per CTA
#define NH 128   // j-half per CTA
#define KC 32    // K chunk

// Scratch (allocation-free rule: __device__ globals). Both halves always
// written every launch -> deterministic, no init needed.
__device__ float g_q2[BN * CN * 2];

// cvt.rna.tf32.f32 writes a .b32 destination; result is fp32-bit-compatible.
__device__ __forceinline__ float tf32r(float a) {
    uint32_t h;
    asm("cvt.rna.tf32.f32 %0, %1;" : "=r"(h) : "f"(a));
    return __uint_as_float(h);
}

// mma.sync m16n8k8 tf32 (sm_80+ baseline PTX; valid on plain sm_100)
__device__ __forceinline__ void mma_tf32(float* c, const uint32_t* a,
                                         const uint32_t* b) {
    asm volatile(
        "mma.sync.aligned.m16n8k8.row.col.f32.tf32.tf32.f32 "
        "{%0,%1,%2,%3}, {%4,%5,%6,%7}, {%8,%9}, {%0,%1,%2,%3};"
        : "+f"(c[0]), "+f"(c[1]), "+f"(c[2]), "+f"(c[3])
        : "r"(a[0]), "r"(a[1]), "r"(a[2]), "r"(a[3]), "r"(b[0]), "r"(b[1]));
}

// ---------------------------------------------------------------------------
// quad_mma_kernel: partial d2 over one j-half:
//   q[b,c,half] = sum_{j in half} ( sum_i sig[c][i][j] * (mu[c,i]-z[b,i]) )^2
// 3xTF32 split (hh + hl + lh) on mma.sync. grid (BN/MT, 2, CN), 256 thr.
// SMEM (64KB dynamic), fragment-order layouts:
//  DhiF/DloF: [(mslot*4+ktile)*32 + (lane^ktile)]*4 + aidx        (16KB each)
//  BhiF/BloF: [(ktile*16+ntile)*32 + (lane^((ntile&15)<<1))]*2+sl (16KB each)
// ---------------------------------------------------------------------------
__global__ __launch_bounds__(256, 2) void quad_mma_kernel(
    const float* __restrict__ z, const float* __restrict__ mu,
    const float* __restrict__ sig) {
    extern __shared__ float sm[];
    float* DhiF = sm;
    float* DloF = sm + 4096;
    float* BhiF = sm + 8192;
    float* BloF = sm + 12288;

    const int btile = blockIdx.x, nh = blockIdx.y, c = blockIdx.z;
    const int b0 = btile * MT, j0 = nh * NH;
    const int tid  = threadIdx.x;
    const int wid  = tid >> 5, lane = tid & 31;

    float acc[16][4];
#pragma unroll
    for (int nt = 0; nt < 16; nt++)
#pragma unroll
        for (int i = 0; i < 4; i++) acc[nt][i] = 0.f;

    const float* sigc = sig + (size_t)c * DN * DN;

    for (int kt = 0; kt < DN / KC; kt++) {
        const int i0 = kt * KC;
        if (kt) __syncthreads();  // previous chunk's reads complete

        // --- stage B: sig[c][i0+ii][j0..j0+127] -> tf32 hi/lo fragments ---
#pragma unroll
        for (int it = 0; it < 4; it++) {
            int idx = tid + it * 256;          // 0..1023
            int ii = idx >> 5, j4 = idx & 31;  // i row, j float4
            float4 v = *(const float4*)(sigc + (size_t)(i0 + ii) * DN + j0 + j4 * 4);
            int ktile = ii >> 3, slot = (ii >> 2) & 1, kl = ii & 3;
            float vv[4] = {v.x, v.y, v.z, v.w};
#pragma unroll
            for (int e = 0; e < 4; e++) {
                int jl = j4 * 4 + e;
                int ntile = jl >> 3;
                int ln = (((jl & 7) * 4 + kl) ^ ((ntile & 15) << 1));
                int off = ((ktile * 16 + ntile) * 32 + ln) * 2 + slot;
                float hi = tf32r(vv[e]);
                BhiF[off] = hi;
                BloF[off] = tf32r(vv[e] - hi);
            }
        }
        // --- stage D: (mu - z) -> tf32 hi/lo fragments ---
#pragma unroll
        for (int it = 0; it < 4; it++) {
            int idx = tid + it * 256;          // 0..1023
            int b = idx >> 3, i4 = idx & 7;
            float4 zv = *(const float4*)(z + (size_t)(b0 + b) * DN + i0 + i4 * 4);
            float4 m4 = *(const float4*)(mu + c * DN + i0 + i4 * 4);
            float dv[4] = {m4.x - zv.x, m4.y - zv.y, m4.z - zv.z, m4.w - zv.w};
            int mslot = b >> 4, r = b & 15;
            int ktile = i4 >> 1;
            int aidx = (r >> 3) + (i4 & 1) * 2;
#pragma unroll
            for (int e = 0; e < 4; e++) {
                int ln = (((r & 7) * 4 + e) ^ ktile);
                int off = ((mslot * 4 + ktile) * 32 + ln) * 4 + aidx;
                float hi = tf32r(dv[e]);
                DhiF[off] = hi;
                DloF[off] = tf32r(dv[e] - hi);
            }
        }
        __syncthreads();

        // --- compute: 4 ktiles x 16 ntiles x {hh, hl, lh} ---
#pragma unroll
        for (int ktile = 0; ktile < 4; ktile++) {
            const int dof = ((wid * 4 + ktile) * 32 + (lane ^ ktile)) * 4;
            float4 ah4 = *(const float4*)&DhiF[dof];
            float4 al4 = *(const float4*)&DloF[dof];
            uint32_t ahi[4] = {__float_as_uint(ah4.x), __float_as_uint(ah4.y),
                               __float_as_uint(ah4.z), __float_as_uint(ah4.w)};
            uint32_t alo[4] = {__float_as_uint(al4.x), __float_as_uint(al4.y),
                               __float_as_uint(al4.z), __float_as_uint(al4.w)};
#pragma unroll
            for (int nt = 0; nt < 16; nt++) {
                const int bof = ((ktile * 16 + nt) * 32 + (lane ^ ((nt & 15) << 1))) * 2;
                float2 bh2 = *(const float2*)&BhiF[bof];
                float2 bl2 = *(const float2*)&BloF[bof];
                uint32_t bh[2] = {__float_as_uint(bh2.x), __float_as_uint(bh2.y)};
                uint32_t bl[2] = {__float_as_uint(bl2.x), __float_as_uint(bl2.y)};
                mma_tf32(acc[nt], ahi, bh);
                mma_tf32(acc[nt], ahi, bl);
                mma_tf32(acc[nt], alo, bh);
            }
        }
    }

    // --- epilogue: square-reduce. c0,c1 -> row g; c2,c3 -> row g+8 ---
    float q0 = 0.f, q1 = 0.f;
#pragma unroll
    for (int nt = 0; nt < 16; nt++) {
        q0 += acc[nt][0] * acc[nt][0] + acc[nt][1] * acc[nt][1];
        q1 += acc[nt][2] * acc[nt][2] + acc[nt][3] * acc[nt][3];
    }
    q0 += __shfl_xor_sync(0xffffffffu, q0, 1);
    q0 += __shfl_xor_sync(0xffffffffu, q0, 2);
    q1 += __shfl_xor_sync(0xffffffffu, q1, 1);
    q1 += __shfl_xor_sync(0xffffffffu, q1, 2);
    if ((lane & 3) == 0) {
        int b = b0 + wid * 16 + (lane >> 2);
        g_q2[((size_t)b * CN + c) * 2 + nh]       = q0;
        g_q2[((size_t)(b + 8) * CN + c) * 2 + nh] = q1;
    }
}

// ---------------------------------------------------------------------------
// Kernel B: d2 -> softmax -> ARX recursion -> weighted output.
// ---------------------------------------------------------------------------
__global__ __launch_bounds__(256) void arx_out_kernel(
    const float* __restrict__ y, const float* __restrict__ u,
    const float* __restrict__ a_coef, const float* __restrict__ b_coef,
    const float* __restrict__ bias, float* __restrict__ out) {
    __shared__ float ps[16 * 16 * 33];
    __shared__ float acs[CN * ORDN];
    __shared__ float bcs[CN * EN];
    __shared__ float bss[CN];

    const int tid = threadIdx.x;
    if (tid < CN * ORDN) acs[tid] = a_coef[tid];
    for (int i = tid; i < CN * EN; i += 256) bcs[i] = b_coef[i];
    if (tid < CN) bss[tid] = bias[tid];
    __syncthreads();

    const int tb = tid >> 4;
    const int tc = tid & 15;
    const int b  = blockIdx.x * 16 + tb;

    float d2 = g_q2[((size_t)b * CN + tc) * 2] + g_q2[((size_t)b * CN + tc) * 2 + 1];
    d2 = fmaxf(d2, 1e-8f);

    float mn = d2;
#pragma unroll
    for (int m = 8; m; m >>= 1) mn = fminf(mn, __shfl_xor_sync(0xffffffffu, mn, m));
    float e = expf(-(d2 - mn));
    float ssum = e;
#pragma unroll
    for (int m = 8; m; m >>= 1) ssum += __shfl_xor_sync(0xffffffffu, ssum, m);
    float psi = e / ssum;

    const float4* uv = (const float4*)(u + ((size_t)b * CN + tc) * EN);
    float ub = bss[tc];
#pragma unroll
    for (int k = 0; k < EN / 4; k++) {
        float4 uu = uv[k];
        const float* bc = &bcs[tc * EN + k * 4];
        ub += uu.x * bc[0] + uu.y * bc[1] + uu.z * bc[2] + uu.w * bc[3];
    }

    float s[ORDN];
    const float4* yv = (const float4*)(y + ((size_t)b * CN + tc) * RN + (RN - ORDN));
#pragma unroll
    for (int k = 0; k < ORDN / 4; k++) {
        float4 t = yv[k];
        s[k * 4 + 0] = t.x; s[k * 4 + 1] = t.y;
        s[k * 4 + 2] = t.z; s[k * 4 + 3] = t.w;
    }
    float ar[ORDN];
#pragma unroll
    for (int o = 0; o < ORDN; o++) ar[o] = acs[tc * ORDN + o];

    float* myps = &ps[(tb * 16 + tc) * 33];
#pragma unroll
    for (int l = 0; l < LN; l++) {
        float y0 = 0.f, y1 = 0.f;
#pragma unroll
        for (int o = 0; o < ORDN; o += 2) {
            y0 += s[o] * ar[o];
            y1 += s[o + 1] * ar[o + 1];
        }
        float yn = ub + y0 + y1;
#pragma unroll
        for (int o = 0; o < ORDN - 1; o++) s[o] = s[o + 1];
        s[ORDN - 1] = yn;
        myps[l] = psi * yn;
    }
    __syncthreads();

    for (int o = tid; o < 16 * LN; o += 256) {
        int bb = o >> 5, l = o & 31;
        float acc = 0.f;
#pragma unroll
        for (int cc = 0; cc < CN; cc++) acc += ps[(bb * 16 + cc) * 33 + l];
        out[(size_t)(blockIdx.x * 16 + bb) * LN + l] = acc;
    }
}

// ---------------------------------------------------------------------------
extern "C" void kernel_launch(void* const* d_in, const int* in_sizes, int n_in,
                              void* d_out, int out_size) {
    const float* y      = (const float*)d_in[0];
    const float* z      = (const float*)d_in[1];
    const float* u      = (const float*)d_in[2];
    const float* mu     = (const float*)d_in[3];
    const float* sig    = (const float*)d_in[4];
    const float* a_coef = (const float*)d_in[5];
    const float* b_coef = (const float*)d_in[6];
    const float* bias   = (const float*)d_in[7];
    float* out = (float*)d_out;

    const int qsmem = 16384 * sizeof(float);  // 64 KB
    cudaFuncSetAttribute(quad_mma_kernel,
                         cudaFuncAttributeMaxDynamicSharedMemorySize, qsmem);

    quad_mma_kernel<<<dim3(BN / MT, 2, CN), 256, qsmem>>>(z, mu, sig);
    arx_out_kernel<<<BN / 16, 256>>>(y, u, a_coef, b_coef, bias, out);
}

// round 9
// speedup vs baseline: 2.9468x; 1.5940x over previous
#include <cuda_runtime.h>
#include <cuda_fp16.h>
#include <cstdint>

#define BN 8192
#define CN 16
#define DN 256
#define RN 64
#define EN 32
#define ORDN 16
#define LN 32

#define MT 128   // bodies per CTA
#define NH 128   // j-half per CTA
#define KC 32    // K chunk (two k16 mma tiles)

// Scratch (__device__ globals; every element written each launch)
__device__ float g_q2[BN * CN * 2];
__device__ float g_m[CN * DN];   // m[c][j] = sum_i sig[c][i][j] * mu[c][i]

// smem u32 layout (per CTA, 33792 B total):
//  Dhi [0,2048)  Dlo [2048,4096)        8 KB each
//  Bhi [4096,6208)  Blo [6208,8320)     8448 B each (33-u32-pair padded rows)
//  mS  [8320,8448)                      128 floats
#define SM_DLO 2048
#define SM_BHI 4096
#define SM_BLO 6208
#define SM_M   8320
#define SM_U32 8448

__device__ __forceinline__ uint32_t pk_h2(float lo_k, float hi_k) {
    __half2 h = __floats2half2_rn(lo_k, hi_k);  // .x = low half = first arg
    return *reinterpret_cast<uint32_t*>(&h);
}

// mma m16n8k16 fp16 -> fp32 accum (sm_80+ baseline; valid on plain sm_100)
__device__ __forceinline__ void mma_f16(float* c, uint4 a, uint2 b) {
    asm volatile(
        "mma.sync.aligned.m16n8k16.row.col.f32.f16.f16.f32 "
        "{%0,%1,%2,%3}, {%4,%5,%6,%7}, {%8,%9}, {%0,%1,%2,%3};"
        : "+f"(c[0]), "+f"(c[1]), "+f"(c[2]), "+f"(c[3])
        : "r"(a.x), "r"(a.y), "r"(a.z), "r"(a.w), "r"(b.x), "r"(b.y));
}

// ---------------------------------------------------------------------------
// m_kernel: g_m[c][j] = sum_i sig[c][i][j] * mu[c][i]. grid CN, block 256.
// ---------------------------------------------------------------------------
__global__ void m_kernel(const float* __restrict__ mu, const float* __restrict__ sig) {
    __shared__ float mus[DN];
    const int c = blockIdx.x, j = threadIdx.x;
    mus[j] = mu[c * DN + j];
    __syncthreads();
    const float* A = sig + (size_t)c * DN * DN;
    float a[8] = {0, 0, 0, 0, 0, 0, 0, 0};
    for (int i = 0; i < DN; i += 8) {
#pragma unroll
        for (int u = 0; u < 8; u++) a[u] += A[(size_t)(i + u) * DN + j] * mus[i + u];
    }
    g_m[c * DN + j] = ((a[0] + a[1]) + (a[2] + a[3])) + ((a[4] + a[5]) + (a[6] + a[7]));
}

// ---------------------------------------------------------------------------
// quad_mma_kernel: V = A^T z via fp16x3 mma; q[b,c,half] = sum_j (V_j - m_j)^2.
// grid (BN/MT, 2, CN), 256 thr, 2 CTAs/SM, single-stage sync (round-7 pattern).
//
// m16n8k16 fragment maps (PTX ISA; g=lane>>2, t=lane&3):
//   A regs a0..a3: (row g|g+8, k-pair t | t+4): reg = rh + 2*sl
//   B regs b0,b1:  (k-pair t | t+4, col g):     reg = sl
//   C regs c0..c3: (row g, col 2t|2t+1), (row g+8, ...)
// ---------------------------------------------------------------------------
__global__ __launch_bounds__(256, 2) void quad_mma_kernel(
    const float* __restrict__ z, const float* __restrict__ sig) {
    extern __shared__ uint32_t smu[];
    const int btile = blockIdx.x, nh = blockIdx.y, c = blockIdx.z;
    const int b0 = btile * MT, j0 = nh * NH;
    const int tid = threadIdx.x, wid = tid >> 5, lane = tid & 31;

    float* mS = (float*)(smu + SM_M);
    if (tid < NH) mS[tid] = g_m[c * DN + j0 + tid];

    float acc[16][4];
#pragma unroll
    for (int nt = 0; nt < 16; nt++)
#pragma unroll
        for (int i = 0; i < 4; i++) acc[nt][i] = 0.f;

    const float* sigc = sig + (size_t)c * DN * DN;
    __half* BhiH = (__half*)(smu + SM_BHI);
    __half* BloH = (__half*)(smu + SM_BLO);

    for (int kt = 0; kt < DN / KC; kt++) {
        const int i0 = kt * KC;
        if (kt) __syncthreads();  // previous chunk's reads complete

        // --- stage D (A operand): z rows, fp16 hi/lo split, fragment order ---
        // thread covers (b, i4): 4 consecutive k -> two full uint32 per array.
#pragma unroll
        for (int it = 0; it < 4; it++) {
            int idx = tid + it * 256;          // 0..1023
            int b = idx >> 3, i4 = idx & 7;
            float4 zv = *(const float4*)(z + (size_t)(b0 + b) * DN + i0 + i4 * 4);
            float v[4] = {zv.x, zv.y, zv.z, zv.w};
            __half h0 = __float2half_rn(v[0]), h1 = __float2half_rn(v[1]);
            __half h2 = __float2half_rn(v[2]), h3 = __float2half_rn(v[3]);
            float l0 = v[0] - __half2float(h0), l1 = v[1] - __half2float(h1);
            float l2 = v[2] - __half2float(h2), l3 = v[3] - __half2float(h3);
            int r = b & 15, g = r & 7, rh = r >> 3, mslot = b >> 4;
            int kt16 = i4 >> 2;
            int sl = (i4 >> 1) & 1;
            int t0 = (i4 & 1) * 2;             // first k-pair's t; second = t0+1
            int reg = rh + 2 * sl;
            int base = ((mslot * 2 + kt16) * 32 + g * 4 + t0) * 4 + reg;
            smu[base]              = pk_h2(__half2float(h0), __half2float(h1));
            smu[base + 4]          = pk_h2(__half2float(h2), __half2float(h3));
            smu[SM_DLO + base]     = pk_h2(l0, l1);
            smu[SM_DLO + base + 4] = pk_h2(l2, l3);
        }
        // --- stage B: sig K-major (k=i, n=j), fp16 hi/lo, padded rows (33) ---
#pragma unroll
        for (int it = 0; it < 4; it++) {
            int idx = tid + it * 256;          // 0..1023
            int ii = idx >> 5, j4 = idx & 31;  // coalesced 512B per warp
            float4 av = *(const float4*)(sigc + (size_t)(i0 + ii) * DN + j0 + j4 * 4);
            float v[4] = {av.x, av.y, av.z, av.w};
            int kk = ii & 15, kt16 = ii >> 4;
            int t = (kk & 7) >> 1, sl = kk >> 3, hp = kk & 1;
#pragma unroll
            for (int e = 0; e < 4; e++) {
                int jl = j4 * 4 + e;
                int nt = jl >> 3, g = jl & 7;
                // u32 idx = ((kt16*16+nt)*33 + g*4+t)*2 + sl ; halves at *2+hp
                int hidx = ((((kt16 * 16 + nt) * 33 + g * 4 + t) * 2 + sl) * 2) + hp;
                __half h = __float2half_rn(v[e]);
                BhiH[hidx] = h;
                BloH[hidx] = __float2half_rn(v[e] - __half2float(h));
            }
        }
        __syncthreads();

        // --- compute: 2 k16-tiles x 16 ntiles x {hh, hl, lh} ---
        const uint4* Dhi4 = (const uint4*)smu;              // 512 uint4
        const uint4* Dlo4 = (const uint4*)(smu + SM_DLO);
        const uint2* Bhi2 = (const uint2*)(smu + SM_BHI);   // padded rows of 33
        const uint2* Blo2 = (const uint2*)(smu + SM_BLO);
#pragma unroll
        for (int ktile = 0; ktile < 2; ktile++) {
            uint4 ah = Dhi4[(wid * 2 + ktile) * 32 + lane];
            uint4 al = Dlo4[(wid * 2 + ktile) * 32 + lane];
#pragma unroll
            for (int nt = 0; nt < 16; nt++) {
                uint2 bh = Bhi2[(ktile * 16 + nt) * 33 + lane];
                uint2 bl = Blo2[(ktile * 16 + nt) * 33 + lane];
                mma_f16(acc[nt], ah, bh);
                mma_f16(acc[nt], ah, bl);
                mma_f16(acc[nt], al, bh);
            }
        }
    }
    __syncthreads();

    // Epilogue: q = sum_j (V_j - m_j)^2.
    float q0 = 0.f, q1 = 0.f;
#pragma unroll
    for (int nt = 0; nt < 16; nt++) {
        float m0 = mS[nt * 8 + (lane & 3) * 2];
        float m1 = mS[nt * 8 + (lane & 3) * 2 + 1];
        float v0 = acc[nt][0] - m0, v1 = acc[nt][1] - m1;
        float v2 = acc[nt][2] - m0, v3 = acc[nt][3] - m1;
        q0 += v0 * v0 + v1 * v1;
        q1 += v2 * v2 + v3 * v3;
    }
    q0 += __shfl_xor_sync(0xffffffffu, q0, 1);
    q0 += __shfl_xor_sync(0xffffffffu, q0, 2);
    q1 += __shfl_xor_sync(0xffffffffu, q1, 1);
    q1 += __shfl_xor_sync(0xffffffffu, q1, 2);
    if ((lane & 3) == 0) {
        int b = b0 + wid * 16 + (lane >> 2);
        g_q2[((size_t)b * CN + c) * 2 + nh]       = q0;
        g_q2[((size_t)(b + 8) * CN + c) * 2 + nh] = q1;
    }
}

// ---------------------------------------------------------------------------
// Kernel B: d2 -> softmax -> ARX recursion -> weighted output.
// ---------------------------------------------------------------------------
__global__ __launch_bounds__(256) void arx_out_kernel(
    const float* __restrict__ y, const float* __restrict__ u,
    const float* __restrict__ a_coef, const float* __restrict__ b_coef,
    const float* __restrict__ bias, float* __restrict__ out) {
    __shared__ float ps[16 * 16 * 33];
    __shared__ float acs[CN * ORDN];
    __shared__ float bcs[CN * EN];
    __shared__ float bss[CN];

    const int tid = threadIdx.x;
    if (tid < CN * ORDN) acs[tid] = a_coef[tid];
    for (int i = tid; i < CN * EN; i += 256) bcs[i] = b_coef[i];
    if (tid < CN) bss[tid] = bias[tid];
    __syncthreads();

    const int tb = tid >> 4;
    const int tc = tid & 15;
    const int b  = blockIdx.x * 16 + tb;

    float d2 = g_q2[((size_t)b * CN + tc) * 2] + g_q2[((size_t)b * CN + tc) * 2 + 1];
    d2 = fmaxf(d2, 1e-8f);

    float mn = d2;
#pragma unroll
    for (int m = 8; m; m >>= 1) mn = fminf(mn, __shfl_xor_sync(0xffffffffu, mn, m));
    float e = expf(-(d2 - mn));
    float ssum = e;
#pragma unroll
    for (int m = 8; m; m >>= 1) ssum += __shfl_xor_sync(0xffffffffu, ssum, m);
    float psi = e / ssum;

    const float4* uv = (const float4*)(u + ((size_t)b * CN + tc) * EN);
    float ub = bss[tc];
#pragma unroll
    for (int k = 0; k < EN / 4; k++) {
        float4 uu = uv[k];
        const float* bc = &bcs[tc * EN + k * 4];
        ub += uu.x * bc[0] + uu.y * bc[1] + uu.z * bc[2] + uu.w * bc[3];
    }

    float s[ORDN];
    const float4* yv = (const float4*)(y + ((size_t)b * CN + tc) * RN + (RN - ORDN));
#pragma unroll
    for (int k = 0; k < ORDN / 4; k++) {
        float4 t = yv[k];
        s[k * 4 + 0] = t.x; s[k * 4 + 1] = t.y;
        s[k * 4 + 2] = t.z; s[k * 4 + 3] = t.w;
    }
    float ar[ORDN];
#pragma unroll
    for (int o = 0; o < ORDN; o++) ar[o] = acs[tc * ORDN + o];

    float* myps = &ps[(tb * 16 + tc) * 33];
#pragma unroll
    for (int l = 0; l < LN; l++) {
        float y0 = 0.f, y1 = 0.f;
#pragma unroll
        for (int o = 0; o < ORDN; o += 2) {
            y0 += s[o] * ar[o];
            y1 += s[o + 1] * ar[o + 1];
        }
        float yn = ub + y0 + y1;
#pragma unroll
        for (int o = 0; o < ORDN - 1; o++) s[o] = s[o + 1];
        s[ORDN - 1] = yn;
        myps[l] = psi * yn;
    }
    __syncthreads();

    for (int o = tid; o < 16 * LN; o += 256) {
        int bb = o >> 5, l = o & 31;
        float acc = 0.f;
#pragma unroll
        for (int cc = 0; cc < CN; cc++) acc += ps[(bb * 16 + cc) * 33 + l];
        out[(size_t)(blockIdx.x * 16 + bb) * LN + l] = acc;
    }
}

// ---------------------------------------------------------------------------
extern "C" void kernel_launch(void* const* d_in, const int* in_sizes, int n_in,
                              void* d_out, int out_size) {
    const float* y      = (const float*)d_in[0];
    const float* z      = (const float*)d_in[1];
    const float* u      = (const float*)d_in[2];
    const float* mu     = (const float*)d_in[3];
    const float* sig    = (const float*)d_in[4];
    const float* a_coef = (const float*)d_in[5];
    const float* b_coef = (const float*)d_in[6];
    const float* bias   = (const float*)d_in[7];
    float* out = (float*)d_out;

    const int qsmem = SM_U32 * sizeof(uint32_t);  // 33792 B
    cudaFuncSetAttribute(quad_mma_kernel,
                         cudaFuncAttributeMaxDynamicSharedMemorySize, qsmem);

    m_kernel<<<CN, DN>>>(mu, sig);
    quad_mma_kernel<<<dim3(BN / MT, 2, CN), 256, qsmem>>>(z, sig);
    arx_out_kernel<<<BN / 16, 256>>>(y, u, a_coef, b_coef, bias, out);
}